// round 7
// baseline (speedup 1.0000x reference)
#include <cuda_runtime.h>
#include <cuda_bf16.h>
#include <cfloat>
#include <cstdint>

// Problem constants
#define B_    256
#define N_    100000
#define D_    512
#define A_    256
#define K_    32
#define C_    100
#define EPS_  1e-8f

// GEMM tiling (mma.sync m16n8k16 bf16, ldmatrix fragments)
#define GM    256              // M tile = all query rows
#define GN    64               // N tile (keys per CTA)
#define BK    16               // k elems per stage (one k16 step)
#define AST   24               // A smem row stride (bf16 elems): 48B rows -> LDSM conflict-free
#define BST   24
#define ASZ   (GM * AST)       // elems per stage
#define BSZ   (GN * BST)
#define NTILE 1563             // ceil(100000/64)
#define N_PAD (NTILE * GN)     // 100032
#define CAND  64               // candidate count per row
#define LK    8                // per-thread local top list

// ---------------- device scratch ----------------
__device__ float          g_q[B_ * D_];
__device__ __nv_bfloat16  g_qhi[B_ * D_];
__device__ float          g_qn[B_];
__device__ float          g_kn[N_];
__device__ float          g_qwq[B_ * A_];
__device__ __nv_bfloat16  g_simh[(size_t)B_ * N_PAD];  // approx sims (bf16)
__device__ int            g_idx[B_ * K_];

// ---------------- helpers ----------------
__device__ __forceinline__ void mma16816(float c[4], const uint32_t a[4],
                                         const uint32_t b[2]) {
    asm volatile(
        "mma.sync.aligned.m16n8k16.row.col.f32.bf16.bf16.f32 "
        "{%0,%1,%2,%3}, {%4,%5,%6,%7}, {%8,%9}, {%0,%1,%2,%3};"
        : "+f"(c[0]), "+f"(c[1]), "+f"(c[2]), "+f"(c[3])
        : "r"(a[0]), "r"(a[1]), "r"(a[2]), "r"(a[3]), "r"(b[0]), "r"(b[1]));
}
__device__ __forceinline__ void ldsm_x4(uint32_t r[4], uint32_t addr) {
    asm volatile("ldmatrix.sync.aligned.m8n8.x4.shared.b16 {%0,%1,%2,%3}, [%4];"
                 : "=r"(r[0]), "=r"(r[1]), "=r"(r[2]), "=r"(r[3]) : "r"(addr));
}
__device__ __forceinline__ uint32_t smem_addr32(const void* p) {
    return (uint32_t)__cvta_generic_to_shared(p);
}

// ---------------- kernel 1: relu + qnorm + bf16 convert + qWq (fused) --------
__global__ __launch_bounds__(256) void relu_qwq_kernel(
    const float* __restrict__ qf, const float* __restrict__ Wq,
    const float* __restrict__ bq) {
    __shared__ float s_q[D_];
    __shared__ float sm[8];
    int b = blockIdx.x, tid = threadIdx.x;
    float s = 0.f;
    #pragma unroll
    for (int u = 0; u < 2; u++) {
        int i = tid + u * 256;
        float v = fmaxf(qf[b * D_ + i], 0.f);
        s_q[i] = v;
        g_q[b * D_ + i] = v;
        g_qhi[b * D_ + i] = __float2bfloat16(v);
        s += v * v;
    }
    for (int o = 16; o; o >>= 1) s += __shfl_down_sync(0xffffffffu, s, o);
    int lane = tid & 31, wrp = tid >> 5;
    if (lane == 0) sm[wrp] = s;
    __syncthreads();
    if (tid == 0) {
        float t = 0.f;
        #pragma unroll
        for (int w = 0; w < 8; w++) t += sm[w];
        g_qn[b] = sqrtf(t);
    }
    // qWq: thread = column a; s_q broadcast via LDS
    float acc = bq[tid];
    #pragma unroll 4
    for (int d = 0; d < D_; d++) acc += s_q[d] * Wq[d * A_ + tid];
    g_qwq[b * A_ + tid] = acc;
}

// ---------------- kernel 2: approx sim GEMM + fused key norms ----------------
// CTA: 256(M) x 64(N), 8 warps as 4(m) x 2(n), warp tile 64x32.
// BK=16 double-buffered stages; fragments via ldmatrix; key ssq accumulated
// during the (single) streaming read of each key row.
__global__ __launch_bounds__(256, 2) void sim_gemm_kernel(const float* __restrict__ keys) {
    __shared__ __nv_bfloat16 As[2][ASZ];
    __shared__ __nv_bfloat16 Bs[2][BSZ];
    __shared__ float knloc[GN];

    int tid = threadIdx.x;
    int wid = tid >> 5, lane = tid & 31;
    int g = lane >> 2, tig = lane & 3;
    int n0cta = blockIdx.x * GN;
    int m0w = (wid >> 1) * 64;
    int n0w = (wid & 1) * 32;

    // per-thread load coords
    int ar = tid >> 1, ac = (tid & 1) * 8;      // A: 2 uint4/thread (rows ar, ar+128)
    int br = tid >> 2, bc = (tid & 3) * 4;      // B: 1 float4/thread, row br
    int nrow = n0cta + br;

    uint32_t as32 = smem_addr32(As);
    uint32_t bs32 = smem_addr32(Bs);

    float c[4][4][4];
    #pragma unroll
    for (int mf = 0; mf < 4; mf++)
        #pragma unroll
        for (int nf = 0; nf < 4; nf++)
            #pragma unroll
            for (int r = 0; r < 4; r++) c[mf][nf][r] = 0.f;

    float ssq = 0.f;

    // ---- prologue: stage 0 (k=0) ----
    {
        uint4 v0 = *(const uint4*)&g_qhi[ar * D_ + ac];
        uint4 v1 = *(const uint4*)&g_qhi[(ar + 128) * D_ + ac];
        *(uint4*)&As[0][ar * AST + ac] = v0;
        *(uint4*)&As[0][(ar + 128) * AST + ac] = v1;
        float4 v = make_float4(0.f, 0.f, 0.f, 0.f);
        if (nrow < N_) v = *(const float4*)&keys[(size_t)nrow * D_ + bc];
        ssq += v.x * v.x + v.y * v.y + v.z * v.z + v.w * v.w;
        __nv_bfloat162 p0 = __floats2bfloat162_rn(v.x, v.y);
        __nv_bfloat162 p1 = __floats2bfloat162_rn(v.z, v.w);
        *(uint2*)&Bs[0][br * BST + bc] =
            make_uint2(*(uint32_t*)&p0, *(uint32_t*)&p1);
    }
    __syncthreads();

    #pragma unroll 1
    for (int t = 0; t < 32; t++) {
        int cur = t & 1, nxt = cur ^ 1;
        int k1 = (t + 1) * BK;
        bool hn = (t < 31);

        uint4 pa0, pa1; float4 pb;
        if (hn) {
            pa0 = *(const uint4*)&g_qhi[ar * D_ + k1 + ac];
            pa1 = *(const uint4*)&g_qhi[(ar + 128) * D_ + k1 + ac];
            pb = (nrow < N_) ? *(const float4*)&keys[(size_t)nrow * D_ + k1 + bc]
                             : make_float4(0.f, 0.f, 0.f, 0.f);
            ssq += pb.x * pb.x + pb.y * pb.y + pb.z * pb.z + pb.w * pb.w;
        }

        // ---- compute one k16 step from stage cur ----
        uint32_t af[4][4], bf[4][2];
        #pragma unroll
        for (int mf = 0; mf < 4; mf++) {
            uint32_t addr = as32 + cur * (ASZ * 2)
                + (uint32_t)(((m0w + mf * 16 + (lane & 15)) * AST + ((lane >> 4) * 8)) * 2);
            ldsm_x4(af[mf], addr);
        }
        #pragma unroll
        for (int p = 0; p < 2; p++) {
            uint32_t r[4];
            uint32_t addr = bs32 + cur * (BSZ * 2)
                + (uint32_t)(((n0w + p * 16 + (lane & 15)) * BST + ((lane >> 4) * 8)) * 2);
            ldsm_x4(r, addr);
            bf[p * 2 + 0][0] = r[0]; bf[p * 2 + 1][0] = r[1];
            bf[p * 2 + 0][1] = r[2]; bf[p * 2 + 1][1] = r[3];
        }
        #pragma unroll
        for (int mf = 0; mf < 4; mf++)
            #pragma unroll
            for (int nf = 0; nf < 4; nf++)
                mma16816(c[mf][nf], af[mf], bf[nf]);

        // ---- commit prefetch into the other stage ----
        if (hn) {
            *(uint4*)&As[nxt][ar * AST + ac] = pa0;
            *(uint4*)&As[nxt][(ar + 128) * AST + ac] = pa1;
            __nv_bfloat162 p0 = __floats2bfloat162_rn(pb.x, pb.y);
            __nv_bfloat162 p1 = __floats2bfloat162_rn(pb.z, pb.w);
            *(uint2*)&Bs[nxt][br * BST + bc] =
                make_uint2(*(uint32_t*)&p0, *(uint32_t*)&p1);
        }
        __syncthreads();
    }

    // ---- key norms: reduce ssq among the 4 lanes sharing a row ----
    {
        float s = ssq;
        s += __shfl_xor_sync(0xffffffffu, s, 1);
        s += __shfl_xor_sync(0xffffffffu, s, 2);
        if ((tid & 3) == 0) {
            float kn = sqrtf(s);
            knloc[br] = kn;
            if (nrow < N_) g_kn[nrow] = kn;
        }
    }
    __syncthreads();

    // ---- epilogue: cosine scaling, bf16 store ----
    #pragma unroll
    for (int mf = 0; mf < 4; mf++) {
        int row0 = m0w + mf * 16 + g;
        float qn0 = g_qn[row0], qn1 = g_qn[row0 + 8];
        #pragma unroll
        for (int nf = 0; nf < 4; nf++) {
            int lc = n0w + nf * 8 + 2 * tig;       // local col (even)
            int col = n0cta + lc;
            if (col < N_) {                         // col even, N_ even => col+1 < N_
                float kn0 = knloc[lc], kn1 = knloc[lc + 1];
                float d00 = fmaxf(qn0 * kn0, EPS_), d01 = fmaxf(qn0 * kn1, EPS_);
                float d10 = fmaxf(qn1 * kn0, EPS_), d11 = fmaxf(qn1 * kn1, EPS_);
                __nv_bfloat162 v0 = __floats2bfloat162_rn(c[mf][nf][0] / d00,
                                                          c[mf][nf][1] / d01);
                __nv_bfloat162 v1 = __floats2bfloat162_rn(c[mf][nf][2] / d10,
                                                          c[mf][nf][3] / d11);
                *(uint32_t*)&g_simh[(size_t)row0 * N_PAD + col]       = *(uint32_t*)&v0;
                *(uint32_t*)&g_simh[(size_t)(row0 + 8) * N_PAD + col] = *(uint32_t*)&v1;
            }
        }
    }
}

// ---------------- kernel 3: top-64 candidates + exact fp32 rescore -> top-32 --
// Warp-contiguous coalesced scan (uint4 = 8 bf16), per-thread top-8,
// 64 block-argmax merge rounds, then in-kernel fp32 rescore of the candidates.
// Padded tail [100000,100032) of g_simh is never written and stays 0 -> never
// competes with real top-64 (all > 0). Downstream attention is permutation-
// invariant in the k-set, so tie-order vs jax.lax.top_k is harmless.
__global__ __launch_bounds__(256) void topk_rescore_kernel(const float* __restrict__ keys) {
    int b = blockIdx.x, tid = threadIdx.x;
    int wid = tid >> 5, lane = tid & 31;

    float lv[LK];
    int   li[LK];
    #pragma unroll
    for (int i = 0; i < LK; i++) { lv[i] = -FLT_MAX; li[i] = 0; }

    const __nv_bfloat16* row = g_simh + (size_t)b * N_PAD;
    int base = wid * (N_PAD / 8);            // 12504 elems per warp, contiguous
    for (int j = lane; j < N_PAD / 8 / 8; j += 32) {   // 1563 uint4 per warp
        uint4 v = *(const uint4*)&row[base + j * 8];
        const __nv_bfloat162* pp = (const __nv_bfloat162*)&v;
        #pragma unroll
        for (int e = 0; e < 4; e++) {
            float v0 = __bfloat162float(pp[e].x);
            float v1 = __bfloat162float(pp[e].y);
            int n0 = base + j * 8 + 2 * e;
            if (v0 > lv[LK - 1]) {
                int q = LK - 1;
                while (q > 0 && v0 > lv[q - 1]) { lv[q] = lv[q - 1]; li[q] = li[q - 1]; q--; }
                lv[q] = v0; li[q] = n0;
            }
            if (v1 > lv[LK - 1]) {
                int q = LK - 1;
                while (q > 0 && v1 > lv[q - 1]) { lv[q] = lv[q - 1]; li[q] = li[q - 1]; q--; }
                lv[q] = v1; li[q] = n0 + 1;
            }
        }
    }

    __shared__ float sv[256];
    __shared__ int   st[256];
    __shared__ int   scand[CAND];
    int p = 0;
    for (int it = 0; it < CAND; it++) {
        sv[tid] = (p < LK) ? lv[p] : -FLT_MAX;
        st[tid] = tid;
        __syncthreads();
        for (int s = 128; s > 0; s >>= 1) {
            if (tid < s) {
                if (sv[tid + s] > sv[tid]) { sv[tid] = sv[tid + s]; st[tid] = st[tid + s]; }
            }
            __syncthreads();
        }
        if (tid == st[0]) {
            scand[it] = li[p];
            p++;
        }
        __syncthreads();
    }

    // ---- exact fp32 rescore of the 64 candidates ----
    __shared__ float simv[CAND];
    __shared__ int   cnt;
    if (tid == 0) cnt = 0;
    __syncthreads();

    float qn = g_qn[b];
    const float4* q4 = (const float4*)(g_q + b * D_);
    for (int ci = wid; ci < CAND; ci += 8) {
        int idx = scand[ci];
        const float4* k4 = (const float4*)(keys + (size_t)idx * D_);
        float s = 0.f;
        #pragma unroll
        for (int j = 0; j < 4; j++) {
            float4 qv = q4[j * 32 + lane];
            float4 kv = k4[j * 32 + lane];
            s += qv.x * kv.x + qv.y * kv.y + qv.z * kv.z + qv.w * kv.w;
        }
        for (int o = 16; o; o >>= 1) s += __shfl_down_sync(0xffffffffu, s, o);
        if (lane == 0) simv[ci] = s / fmaxf(qn * g_kn[idx], EPS_);
    }
    __syncthreads();

    // rank by counting; keep top-32 set (stable tie-break by slot)
    if (tid < CAND) {
        float v = simv[tid];
        int r = 0;
        #pragma unroll
        for (int j = 0; j < CAND; j++)
            r += (simv[j] > v) || (simv[j] == v && j < tid);
        if (r < K_) {
            int pos = atomicAdd(&cnt, 1);
            g_idx[b * K_ + pos] = scand[tid];
        }
    }
}

// ---------------- kernel 4: attention MLP + softmax + classifier ----------------
// knn staged through smem in 4 chunks of 128 cols -> the hot macc loop reads
// broadcast LDS instead of 4096 redundant uniform LDGs per thread.
__global__ __launch_bounds__(256) void attn_out_kernel(
    const float* __restrict__ keys,
    const float* __restrict__ Wm, const float* __restrict__ bm,
    const float* __restrict__ Ws, const float* __restrict__ bs,
    const float* __restrict__ Wc, const float* __restrict__ bc,
    float* __restrict__ out) {
    int b = blockIdx.x, tid = threadIdx.x;   // tid == column a of A_
    __shared__ int   s_idx[K_];
    __shared__ float s_knn[K_][128];
    __shared__ float s_red[8][K_];
    __shared__ float s_w[K_];
    __shared__ float s_att[D_];
    if (tid < K_) s_idx[tid] = g_idx[b * K_ + tid];
    __syncthreads();

    float macc[K_];
    float bma = bm[tid];
    #pragma unroll
    for (int k = 0; k < K_; k++) macc[k] = bma;

    for (int ch = 0; ch < 4; ch++) {
        // load chunk: 32 rows x 128 cols
        #pragma unroll
        for (int u = 0; u < 4; u++) {
            int i = tid + u * 256;
            int r = i >> 5, c4 = (i & 31) * 4;
            *(float4*)&s_knn[r][c4] =
                *(const float4*)&keys[(size_t)s_idx[r] * D_ + ch * 128 + c4];
        }
        __syncthreads();
        for (int ds = 0; ds < 32; ds++) {
            int d = ch * 128 + ds * 4;
            float w0 = Wm[(d + 0) * A_ + tid];
            float w1 = Wm[(d + 1) * A_ + tid];
            float w2 = Wm[(d + 2) * A_ + tid];
            float w3 = Wm[(d + 3) * A_ + tid];
            #pragma unroll
            for (int k = 0; k < K_; k++) {
                float4 kv = *(const float4*)&s_knn[k][ds * 4];
                macc[k] += kv.x * w0 + kv.y * w1 + kv.z * w2 + kv.w * w3;
            }
        }
        __syncthreads();
    }

    // score_k = sum_a tanh(qwq[a] + macc[k]) * Ws[a]  (+ bs)
    float qa  = g_qwq[b * A_ + tid];
    float wsa = Ws[tid];
    int lane = tid & 31, wrp = tid >> 5;
    for (int k = 0; k < K_; k++) {
        float t = tanhf(qa + macc[k]) * wsa;
        for (int o = 16; o; o >>= 1) t += __shfl_down_sync(0xffffffffu, t, o);
        if (lane == 0) s_red[wrp][k] = t;
    }
    __syncthreads();

    // softmax over K (warp 0)
    if (tid < K_) {
        float s = bs[0];
        #pragma unroll
        for (int w = 0; w < 8; w++) s += s_red[w][tid];
        float m = s;
        for (int o = 16; o; o >>= 1) m = fmaxf(m, __shfl_xor_sync(0xffffffffu, m, o));
        float e = expf(s - m);
        float tot = e;
        for (int o = 16; o; o >>= 1) tot += __shfl_xor_sync(0xffffffffu, tot, o);
        s_w[tid] = e / tot;
    }
    __syncthreads();

    // attended = sum_k w_k * knn_k
    for (int d = tid; d < D_; d += 256) {
        float a = 0.f;
        #pragma unroll
        for (int k = 0; k < K_; k++) a += s_w[k] * keys[(size_t)s_idx[k] * D_ + d];
        s_att[d] = a;
    }
    __syncthreads();

    // out[b][c] = [q, attended] @ Wc + bc
    for (int c = tid; c < C_; c += 256) {
        float acc = bc[c];
        const float* qrow = g_q + b * D_;
        #pragma unroll 4
        for (int j = 0; j < D_; j++) acc += qrow[j] * Wc[j * C_ + c];
        #pragma unroll 4
        for (int j = 0; j < D_; j++) acc += s_att[j] * Wc[(D_ + j) * C_ + c];
        out[b * C_ + c] = acc;
    }
}

// ---------------- launch ----------------
extern "C" void kernel_launch(void* const* d_in, const int* in_sizes, int n_in,
                              void* d_out, int out_size) {
    const float* query_feat = (const float*)d_in[0];
    const float* keys       = (const float*)d_in[1];
    const float* Wq         = (const float*)d_in[2];
    const float* bq         = (const float*)d_in[3];
    const float* Wm         = (const float*)d_in[4];
    const float* bm         = (const float*)d_in[5];
    const float* Ws         = (const float*)d_in[6];
    const float* bs         = (const float*)d_in[7];
    const float* Wc         = (const float*)d_in[8];
    const float* bc         = (const float*)d_in[9];
    float* out = (float*)d_out;

    relu_qwq_kernel<<<B_, 256>>>(query_feat, Wq, bq);
    sim_gemm_kernel<<<NTILE, 256>>>(keys);
    topk_rescore_kernel<<<B_, 256>>>(keys);
    attn_out_kernel<<<B_, 256>>>(keys, Wm, bm, Ws, bs, Wc, bc, out);
}